// round 15
// baseline (speedup 1.0000x reference)
#include <cuda_runtime.h>
#include <cuda_bf16.h>
#include <mma.h>
#include <math.h>

using namespace nvcuda;

// ---------------------------------------------------------------------------
// Problem constants
// ---------------------------------------------------------------------------
#define R_ROIS  256
#define C_CH    256
#define POOL    7
#define KDIM    (C_CH * POOL * POOL)   // 12544
#define NH1     1024
#define NCLSLOC 84
#define NSCORE  21
#define NHEADS  (NCLSLOC + NSCORE)     // 105

// ---------------------------------------------------------------------------
// Scratch (device globals; no allocation allowed)
// ---------------------------------------------------------------------------
__device__ float          g_pooled[R_ROIS * KDIM];
__device__ __nv_bfloat16  g_Ahi[R_ROIS * KDIM];
__device__ __nv_bfloat16  g_Alo[R_ROIS * KDIM];
__device__ __nv_bfloat16  g_w1hi[NH1 * KDIM];
__device__ __nv_bfloat16  g_w1lo[NH1 * KDIM];
__device__ float          g_part1[4 * R_ROIS * NH1];
__device__ float          g_h1[R_ROIS * NH1];
__device__ __nv_bfloat16  g_h1hi[R_ROIS * NH1];
__device__ __nv_bfloat16  g_h1lo[R_ROIS * NH1];
__device__ __nv_bfloat16  g_w2hi[NH1 * NH1];
__device__ __nv_bfloat16  g_w2lo[NH1 * NH1];
__device__ float          g_part2[2 * R_ROIS * NH1];
__device__ float          g_h2[R_ROIS * NH1];

// ---------------------------------------------------------------------------
// RoI max-pool — VALIDATED (R12). Math is PROTECTED; do not modify.
// ---------------------------------------------------------------------------
__global__ void __launch_bounds__(C_CH) pool_kernel(
    const float* __restrict__ f2, const float* __restrict__ f3,
    const float* __restrict__ f4, const float* __restrict__ f5,
    const float* __restrict__ rois, const int* __restrict__ ridx,
    const int* __restrict__ img_h_p, float* __restrict__ pooled)
{
    const int r = blockIdx.x;
    const int c = threadIdx.x;

    float y1 = rois[r * 4 + 0], x1 = rois[r * 4 + 1];
    float y2 = rois[r * 4 + 2], x2 = rois[r * 4 + 3];

    float hh  = __fadd_rn(__fsub_rn(y2, y1), 1.0f);
    float wwf = __fadd_rn(__fsub_rn(x2, x1), 1.0f);
    float area = __fmul_rn(hh, wwf);
    float s    = __fsqrt_rn(area);
    float xarg = __fdiv_rn(s, 224.0f);
    float vlog = (float)log((double)xarg);
    float v    = __fadd_rn(vlog, 4.0f);
    float lv   = rintf(v);
    lv = fminf(fmaxf(lv, 2.0f), 5.0f);
    int lvl = (int)lv;

    const float* feat; int H;
    if      (lvl == 2) { feat = f2; H = 200; }
    else if (lvl == 3) { feat = f3; H = 100; }
    else if (lvl == 4) { feat = f4; H = 50;  }
    else               { feat = f5; H = 25;  }
    const int W = H;

    float imgh  = img_h_p ? (float)(*img_h_p) : 800.0f;
    float scale = __fdiv_rn((float)H, imgh);

    int rsw = (int)rintf(__fmul_rn(x1, scale));
    int rsh = (int)rintf(__fmul_rn(y1, scale));
    int rew = (int)rintf(__fmul_rn(x2, scale));
    int reh = (int)rintf(__fmul_rn(y2, scale));
    float roi_w = fmaxf((float)(rew - rsw + 1), 1.0f);
    float roi_h = fmaxf((float)(reh - rsh + 1), 1.0f);

    const float INV7 = 1.0f / 7.0f;            // PROTECTED: XLA div-by-const
    float rw7 = __fmul_rn(roi_w, INV7);
    float rh7 = __fmul_rn(roi_h, INV7);

    int hs[POOL], he[POOL], ws[POOL], we[POOL];
    #pragma unroll
    for (int p = 0; p < POOL; p++) {
        hs[p] = min(max((int)floorf(__fmul_rn((float)p,       rh7)) + rsh, 0), H);
        he[p] = min(max((int)ceilf (__fmul_rn((float)(p + 1), rh7)) + rsh, 0), H);
        ws[p] = min(max((int)floorf(__fmul_rn((float)p,       rw7)) + rsw, 0), W);
        we[p] = min(max((int)ceilf (__fmul_rn((float)(p + 1), rw7)) + rsw, 0), W);
    }

    const float* fb = feat + (size_t)(ridx[r] * C_CH + c) * H * W;
    float* outp = pooled + (size_t)r * KDIM + c * (POOL * POOL);

    #pragma unroll
    for (int ph = 0; ph < POOL; ph++) {
        int ys  = hs[ph];
        int yeF = he[ph];
        int ye  = min(yeF, ys + 6);
        #pragma unroll
        for (int pw = 0; pw < POOL; pw++) {
            int xs  = ws[pw];
            int xeF = we[pw];
            int xe  = min(xeF, xs + 6);
            float best;
            if (yeF <= ys || xeF <= xs) {
                best = 0.0f;
            } else {
                best = -INFINITY;
                for (int y = ys; y < ye; y++) {
                    const float* rowp = fb + (size_t)y * W;
                    for (int x = xs; x < xe; x++)
                        best = fmaxf(best, rowp[x]);
                }
            }
            outp[ph * POOL + pw] = best;
        }
    }
}

// ---------------------------------------------------------------------------
// fp32 -> (hi, lo) bf16 split.  x = hi + lo + O(2^-17 x)
// ---------------------------------------------------------------------------
__global__ void split_bf16_kernel(const float* __restrict__ x,
                                  __nv_bfloat16* __restrict__ hi,
                                  __nv_bfloat16* __restrict__ lo, int n)
{
    int i = blockIdx.x * blockDim.x + threadIdx.x;
    int i4 = i * 4;
    if (i4 + 3 < n) {
        float4 v = *(const float4*)(x + i4);
        __nv_bfloat16 h0 = __float2bfloat16_rn(v.x);
        __nv_bfloat16 h1 = __float2bfloat16_rn(v.y);
        __nv_bfloat16 h2 = __float2bfloat16_rn(v.z);
        __nv_bfloat16 h3 = __float2bfloat16_rn(v.w);
        __nv_bfloat162 hv0; hv0.x = h0; hv0.y = h1;
        __nv_bfloat162 hv1; hv1.x = h2; hv1.y = h3;
        *(__nv_bfloat162*)(hi + i4)     = hv0;
        *(__nv_bfloat162*)(hi + i4 + 2) = hv1;
        __nv_bfloat162 lv0, lv1;
        lv0.x = __float2bfloat16_rn(v.x - __bfloat162float(h0));
        lv0.y = __float2bfloat16_rn(v.y - __bfloat162float(h1));
        lv1.x = __float2bfloat16_rn(v.z - __bfloat162float(h2));
        lv1.y = __float2bfloat16_rn(v.w - __bfloat162float(h3));
        *(__nv_bfloat162*)(lo + i4)     = lv0;
        *(__nv_bfloat162*)(lo + i4 + 2) = lv1;
    } else {
        for (int k = i4; k < n; k++) {
            float v = x[k];
            __nv_bfloat16 h = __float2bfloat16_rn(v);
            hi[k] = h;
            lo[k] = __float2bfloat16_rn(v - __bfloat162float(h));
        }
    }
}

// ---------------------------------------------------------------------------
// Split-K split-bf16 tensor-core GEMM:
//   Cpart[z] = Ahi*Bhi^T + Ahi*Blo^T + Alo*Bhi^T   over K slice z
// A: [M][K] row-major (hi/lo), B: [N][K] row-major (hi/lo).
// grid (N/64, M/64, S), block 128 (4 warps, each 32x32 out).
// ---------------------------------------------------------------------------
__global__ void __launch_bounds__(128) gemm_bf16_splitk(
    const __nv_bfloat16* __restrict__ Ahi, const __nv_bfloat16* __restrict__ Alo,
    const __nv_bfloat16* __restrict__ Bhi, const __nv_bfloat16* __restrict__ Blo,
    float* __restrict__ Cpart, int M, int N, int K, int kchunk)
{
    __shared__ __nv_bfloat16 sAh[64 * 16];
    __shared__ __nv_bfloat16 sAl[64 * 16];
    __shared__ __nv_bfloat16 sBh[64 * 16];
    __shared__ __nv_bfloat16 sBl[64 * 16];

    const int t  = threadIdx.x;
    const int m0 = blockIdx.y * 64;
    const int n0 = blockIdx.x * 64;
    const int ks = blockIdx.z * kchunk;
    const int ke = ks + kchunk;

    const int warp = t >> 5;
    const int wm = (warp >> 1) * 32;      // 0 or 32
    const int wn = (warp & 1) * 32;       // 0 or 32

    wmma::fragment<wmma::accumulator, 16, 16, 16, float> acc[2][2];
    #pragma unroll
    for (int i = 0; i < 2; i++)
        #pragma unroll
        for (int j = 0; j < 2; j++)
            wmma::fill_fragment(acc[i][j], 0.0f);

    const int row  = t >> 1;              // 0..63
    const int half = t & 1;               // 0,1  (8 bf16 = 16B each)
    const size_t aoff = (size_t)(m0 + row) * K + half * 8;
    const size_t boff = (size_t)(n0 + row) * K + half * 8;
    const int soff = row * 16 + half * 8;

    for (int kt = ks; kt < ke; kt += 16) {
        *(uint4*)&sAh[soff] = *(const uint4*)&Ahi[aoff + kt];
        *(uint4*)&sAl[soff] = *(const uint4*)&Alo[aoff + kt];
        *(uint4*)&sBh[soff] = *(const uint4*)&Bhi[boff + kt];
        *(uint4*)&sBl[soff] = *(const uint4*)&Blo[boff + kt];
        __syncthreads();

        wmma::fragment<wmma::matrix_a, 16, 16, 16, __nv_bfloat16, wmma::row_major> ah[2], al[2];
        wmma::fragment<wmma::matrix_b, 16, 16, 16, __nv_bfloat16, wmma::col_major> bh[2], bl[2];
        #pragma unroll
        for (int i = 0; i < 2; i++) {
            wmma::load_matrix_sync(ah[i], &sAh[(wm + i * 16) * 16], 16);
            wmma::load_matrix_sync(al[i], &sAl[(wm + i * 16) * 16], 16);
            wmma::load_matrix_sync(bh[i], &sBh[(wn + i * 16) * 16], 16);
            wmma::load_matrix_sync(bl[i], &sBl[(wn + i * 16) * 16], 16);
        }

        #pragma unroll
        for (int i = 0; i < 2; i++)
            #pragma unroll
            for (int j = 0; j < 2; j++) {
                wmma::mma_sync(acc[i][j], ah[i], bh[j], acc[i][j]);
                wmma::mma_sync(acc[i][j], ah[i], bl[j], acc[i][j]);
                wmma::mma_sync(acc[i][j], al[i], bh[j], acc[i][j]);
            }
        __syncthreads();
    }

    float* Cp = Cpart + (size_t)blockIdx.z * M * N;
    #pragma unroll
    for (int i = 0; i < 2; i++)
        #pragma unroll
        for (int j = 0; j < 2; j++)
            wmma::store_matrix_sync(&Cp[(size_t)(m0 + wm + i * 16) * N + (n0 + wn + j * 16)],
                                    acc[i][j], N, wmma::mem_row_major);
}

// ---------------------------------------------------------------------------
// out[i] = relu( sum_s part[s][i] + bias[i % N] )
// ---------------------------------------------------------------------------
__global__ void reduce_bias_relu(const float* __restrict__ part,
                                 const float* __restrict__ bias,
                                 float* __restrict__ out,
                                 int S, int MN, int N)
{
    int i = blockIdx.x * blockDim.x + threadIdx.x;
    if (i >= MN) return;
    float s = bias[i % N];
    for (int ss = 0; ss < S; ss++) s += part[(size_t)ss * MN + i];
    out[i] = fmaxf(s, 0.0f);
}

// ---------------------------------------------------------------------------
// Heads GEMM (fp32, 8 CTAs) — validated R13
// ---------------------------------------------------------------------------
__global__ void __launch_bounds__(256) heads_gemm(
    const float* __restrict__ h2,
    const float* __restrict__ clw, const float* __restrict__ clb,
    const float* __restrict__ scw, const float* __restrict__ scb,
    float* __restrict__ out)
{
    __shared__ float As[16][68];
    __shared__ float Bs[16][68];

    const int t  = threadIdx.x;
    const int m0 = blockIdx.y * 64;
    const int n0 = blockIdx.x * 64;

    const int arow = t >> 2;
    const int ac4  = (t & 3) << 2;
    const float* Ag = h2 + (size_t)(m0 + arow) * NH1 + ac4;

    const int brow = n0 + arow;
    const float* Bg = nullptr;
    if      (brow < NCLSLOC) Bg = clw + (size_t)brow * NH1 + ac4;
    else if (brow < NHEADS)  Bg = scw + (size_t)(brow - NCLSLOC) * NH1 + ac4;

    float acc[4][4];
    #pragma unroll
    for (int i = 0; i < 4; i++)
        #pragma unroll
        for (int j = 0; j < 4; j++) acc[i][j] = 0.0f;

    const int tm = (t >> 4) << 2;
    const int tn = (t & 15) << 2;

    for (int kt = 0; kt < NH1; kt += 16) {
        float4 av = *(const float4*)(Ag + kt);
        float4 bv = Bg ? *(const float4*)(Bg + kt) : make_float4(0.f, 0.f, 0.f, 0.f);
        As[ac4 + 0][arow] = av.x; As[ac4 + 1][arow] = av.y;
        As[ac4 + 2][arow] = av.z; As[ac4 + 3][arow] = av.w;
        Bs[ac4 + 0][arow] = bv.x; Bs[ac4 + 1][arow] = bv.y;
        Bs[ac4 + 2][arow] = bv.z; Bs[ac4 + 3][arow] = bv.w;
        __syncthreads();

        #pragma unroll
        for (int kk = 0; kk < 16; kk++) {
            float4 a = *(const float4*)&As[kk][tm];
            float4 b = *(const float4*)&Bs[kk][tn];
            acc[0][0] += a.x * b.x; acc[0][1] += a.x * b.y; acc[0][2] += a.x * b.z; acc[0][3] += a.x * b.w;
            acc[1][0] += a.y * b.x; acc[1][1] += a.y * b.y; acc[1][2] += a.y * b.z; acc[1][3] += a.y * b.w;
            acc[2][0] += a.z * b.x; acc[2][1] += a.z * b.y; acc[2][2] += a.z * b.z; acc[2][3] += a.z * b.w;
            acc[3][0] += a.w * b.x; acc[3][1] += a.w * b.y; acc[3][2] += a.w * b.z; acc[3][3] += a.w * b.w;
        }
        __syncthreads();
    }

    #pragma unroll
    for (int i = 0; i < 4; i++) {
        const int r = m0 + tm + i;
        #pragma unroll
        for (int j = 0; j < 4; j++) {
            const int o = n0 + tn + j;
            if (o < NCLSLOC) {
                out[(size_t)r * NCLSLOC + o] = acc[i][j] + clb[o];
            } else if (o < NHEADS) {
                const int oo = o - NCLSLOC;
                out[(size_t)R_ROIS * NCLSLOC + (size_t)r * NSCORE + oo] =
                    acc[i][j] + scb[oo];
            }
        }
    }
}

// ---------------------------------------------------------------------------
// Launch
// ---------------------------------------------------------------------------
extern "C" void kernel_launch(void* const* d_in, const int* in_sizes, int n_in,
                              void* d_out, int out_size)
{
    const float* f2   = (const float*)d_in[0];
    const float* f3   = (const float*)d_in[1];
    const float* f4   = (const float*)d_in[2];
    const float* f5   = (const float*)d_in[3];
    const float* rois = (const float*)d_in[4];
    const int*   ridx = (const int*)d_in[5];
    const float* w1   = (const float*)d_in[6];
    const float* b1   = (const float*)d_in[7];
    const float* w2   = (const float*)d_in[8];
    const float* b2   = (const float*)d_in[9];
    const float* clw  = (const float*)d_in[10];
    const float* clb  = (const float*)d_in[11];
    const float* scw  = (const float*)d_in[12];
    const float* scb  = (const float*)d_in[13];
    const int*   imgh = (n_in > 14) ? (const int*)d_in[14] : nullptr;
    float* out = (float*)d_out;

    float *pooled, *part1, *h1, *part2, *h2;
    __nv_bfloat16 *Ahi, *Alo, *w1hi, *w1lo, *h1hi, *h1lo, *w2hi, *w2lo;
    cudaGetSymbolAddress((void**)&pooled, g_pooled);
    cudaGetSymbolAddress((void**)&Ahi,    g_Ahi);
    cudaGetSymbolAddress((void**)&Alo,    g_Alo);
    cudaGetSymbolAddress((void**)&w1hi,   g_w1hi);
    cudaGetSymbolAddress((void**)&w1lo,   g_w1lo);
    cudaGetSymbolAddress((void**)&part1,  g_part1);
    cudaGetSymbolAddress((void**)&h1,     g_h1);
    cudaGetSymbolAddress((void**)&h1hi,   g_h1hi);
    cudaGetSymbolAddress((void**)&h1lo,   g_h1lo);
    cudaGetSymbolAddress((void**)&w2hi,   g_w2hi);
    cudaGetSymbolAddress((void**)&w2lo,   g_w2lo);
    cudaGetSymbolAddress((void**)&part2,  g_part2);
    cudaGetSymbolAddress((void**)&h2,     g_h2);

    // 1) RoI max-pool
    pool_kernel<<<R_ROIS, C_CH>>>(f2, f3, f4, f5, rois, ridx, imgh, pooled);

    // 2) bf16 splits (pooled, w1) — w1 split can overlap pool on the stream
    {
        int n = NH1 * KDIM;
        split_bf16_kernel<<<(n / 4 + 255) / 256, 256>>>(w1, w1hi, w1lo, n);
        n = R_ROIS * KDIM;
        split_bf16_kernel<<<(n / 4 + 255) / 256, 256>>>(pooled, Ahi, Alo, n);
    }

    // 3) fc1: split-bf16 tensor GEMM, split-K=4 (256 CTAs)
    gemm_bf16_splitk<<<dim3(NH1 / 64, R_ROIS / 64, 4), 128>>>(
        Ahi, Alo, w1hi, w1lo, part1, R_ROIS, NH1, KDIM, KDIM / 4);
    reduce_bias_relu<<<(R_ROIS * NH1 + 255) / 256, 256>>>(
        part1, b1, h1, 4, R_ROIS * NH1, NH1);

    // 4) fc2: split-bf16 tensor GEMM, split-K=2 (128 CTAs)
    {
        int n = NH1 * NH1;
        split_bf16_kernel<<<(n / 4 + 255) / 256, 256>>>(w2, w2hi, w2lo, n);
        n = R_ROIS * NH1;
        split_bf16_kernel<<<(n / 4 + 255) / 256, 256>>>(h1, h1hi, h1lo, n);
    }
    gemm_bf16_splitk<<<dim3(NH1 / 64, R_ROIS / 64, 2), 128>>>(
        h1hi, h1lo, w2hi, w2lo, part2, R_ROIS, NH1, NH1, NH1 / 2);
    reduce_bias_relu<<<(R_ROIS * NH1 + 255) / 256, 256>>>(
        part2, b2, h2, 2, R_ROIS * NH1, NH1);

    // 5) heads
    heads_gemm<<<dim3(2, R_ROIS / 64), 256>>>(h2, clw, clb, scw, scb, out);
}